// round 8
// baseline (speedup 1.0000x reference)
#include <cuda_runtime.h>
#include <math.h>

#define DT 0.05f
#define NSTEPS 4
#define NTHREADS 256
#define PTS 32          // points per block (8 threads each)
#define TSTR 20         // tile row stride (floats): conflict-free, 16B aligned
#define PPB 836         // floats per point (mod 32 == 4 -> bank stagger)
#define TILE_OFF 0      // 320 floats
#define S_OFF 320       // 256 floats: S0 stash, later S_new for transpose
#define F_OFF 576       // 256 floats: F accumulator stash
#define SMEM_BYTES (PTS * PPB * 4)

typedef unsigned long long u64;

__device__ __forceinline__ u64 pack2(float x, float y) {
    u64 r;
    asm("mov.b64 %0, {%1, %2};" : "=l"(r) : "f"(x), "f"(y));
    return r;
}
__device__ __forceinline__ void unpack2(u64 v, float& x, float& y) {
    asm("mov.b64 {%0, %1}, %2;" : "=f"(x), "=f"(y) : "l"(v));
}
__device__ __forceinline__ void fma2(u64& d, u64 a, u64 b) {
    asm("fma.rn.f32x2 %0, %1, %2, %0;" : "+l"(d) : "l"(a), "l"(b));
}

// Write this thread's two rows (q, q+8) into the stride-TSTR tile.
__device__ __forceinline__ void put2(float* tile, int q, const float v0[16],
                                     const float v1[16]) {
    __syncwarp();
    float4* d0 = (float4*)(tile + q * TSTR);
    float4* d1 = (float4*)(tile + (q + 8) * TSTR);
    d0[0] = make_float4(v0[0], v0[1], v0[2], v0[3]);
    d0[1] = make_float4(v0[4], v0[5], v0[6], v0[7]);
    d0[2] = make_float4(v0[8], v0[9], v0[10], v0[11]);
    d0[3] = make_float4(v0[12], v0[13], v0[14], v0[15]);
    d1[0] = make_float4(v1[0], v1[1], v1[2], v1[3]);
    d1[1] = make_float4(v1[4], v1[5], v1[6], v1[7]);
    d1[2] = make_float4(v1[8], v1[9], v1[10], v1[11]);
    d1[3] = make_float4(v1[12], v1[13], v1[14], v1[15]);
    __syncwarp();
}

// Core FMA block shared by both matmul variants.
#define MM_BODY(BSTR)                                                        \
    _Pragma("unroll")                                                        \
    for (int k = 0; k < 16; k++) {                                           \
        const ulonglong2* bp = (const ulonglong2*)(Bs + k * (BSTR));         \
        ulonglong2 ba = bp[0], bb = bp[1], bc = bp[2], bd = bp[3];           \
        u64 ak0 = pack2(a0[k], a0[k]);                                       \
        u64 ak1 = pack2(a1[k], a1[k]);                                       \
        fma2(acc0[0], ak0, ba.x); fma2(acc0[1], ak0, ba.y);                  \
        fma2(acc0[2], ak0, bb.x); fma2(acc0[3], ak0, bb.y);                  \
        fma2(acc0[4], ak0, bc.x); fma2(acc0[5], ak0, bc.y);                  \
        fma2(acc0[6], ak0, bd.x); fma2(acc0[7], ak0, bd.y);                  \
        fma2(acc1[0], ak1, ba.x); fma2(acc1[1], ak1, ba.y);                  \
        fma2(acc1[2], ak1, bb.x); fma2(acc1[3], ak1, bb.y);                  \
        fma2(acc1[4], ak1, bc.x); fma2(acc1[5], ak1, bc.y);                  \
        fma2(acc1[6], ak1, bd.x); fma2(acc1[7], ak1, bd.y);                  \
    }

// c{0,1} = a{0,1} * B   (zero-init)
template <int BSTR>
__device__ __forceinline__ void mm2z(float c0[16], float c1[16],
                                     const float a0[16], const float a1[16],
                                     const float* Bs) {
    u64 acc0[8], acc1[8];
#pragma unroll
    for (int i = 0; i < 8; i++) { acc0[i] = 0ULL; acc1[i] = 0ULL; }
    MM_BODY(BSTR)
#pragma unroll
    for (int i = 0; i < 8; i++) {
        unpack2(acc0[i], c0[2 * i], c0[2 * i + 1]);
        unpack2(acc1[i], c1[2 * i], c1[2 * i + 1]);
    }
}

// c{0,1} += a{0,1} * B
template <int BSTR>
__device__ __forceinline__ void mm2a(float c0[16], float c1[16],
                                     const float a0[16], const float a1[16],
                                     const float* Bs) {
    u64 acc0[8], acc1[8];
#pragma unroll
    for (int i = 0; i < 8; i++) {
        acc0[i] = pack2(c0[2 * i], c0[2 * i + 1]);
        acc1[i] = pack2(c1[2 * i], c1[2 * i + 1]);
    }
    MM_BODY(BSTR)
#pragma unroll
    for (int i = 0; i < 8; i++) {
        unpack2(acc0[i], c0[2 * i], c0[2 * i + 1]);
        unpack2(acc1[i], c1[2 * i], c1[2 * i + 1]);
    }
}

__device__ __forceinline__ void ld_row16(float v[16], const float* src) {
    const float4* s = (const float4*)src;
#pragma unroll
    for (int i = 0; i < 4; i++) {
        float4 t = s[i];
        v[4 * i + 0] = t.x; v[4 * i + 1] = t.y;
        v[4 * i + 2] = t.z; v[4 * i + 3] = t.w;
    }
}
__device__ __forceinline__ void st_row16(float* dst, const float v[16]) {
    float4* d = (float4*)dst;
    d[0] = make_float4(v[0], v[1], v[2], v[3]);
    d[1] = make_float4(v[4], v[5], v[6], v[7]);
    d[2] = make_float4(v[8], v[9], v[10], v[11]);
    d[3] = make_float4(v[12], v[13], v[14], v[15]);
}

__global__ void __launch_bounds__(NTHREADS, 2)
ham_kernel(const float* __restrict__ mu, const float* __restrict__ Sigma,
           const float* __restrict__ phi, const float* __restrict__ pi_mu,
           const float* __restrict__ pi_Sigma, const float* __restrict__ pi_phi,
           const float* __restrict__ M_inv,
           float* __restrict__ mu_o, float* __restrict__ Sig_o,
           float* __restrict__ phi_o) {
    extern __shared__ float smem[];
    const int tid = threadIdx.x;
    const int lp = tid >> 3;   // local point 0..31
    const int q = tid & 7;     // owns rows q and q+8
    const int r1 = q + 8;
    const int p = blockIdx.x * PTS + lp;
    float* tile = smem + lp * PPB + TILE_OFF;
    float* Ss = smem + lp * PPB + S_OFF;   // stride 16
    float* Fs = smem + lp * PPB + F_OFF;   // stride 16

    // Three register row-pairs: W, T, G (96 floats) + transient accumulators.
    float W0[16], W1[16], T0[16], T1[16], G0[16], G1[16];

    // ---- stash S0; load P ----
    ld_row16(T0, Sigma + (size_t)p * 256 + q * 16);
    ld_row16(T1, Sigma + (size_t)p * 256 + r1 * 16);
    st_row16(Ss + q * 16, T0);
    st_row16(Ss + r1 * 16, T1);
    ld_row16(G0, pi_Sigma + (size_t)p * 256 + q * 16);
    ld_row16(G1, pi_Sigma + (size_t)p * 256 + r1 * 16);

    // ---- mu update (rows q, q+8): mu + NSTEPS*dt * M_inv @ pi_mu ----
    {
        float pmv[16];
        ld_row16(pmv, pi_mu + (size_t)p * 16);
        const float* M0 = M_inv + (size_t)p * 256 + q * 16;
        const float* M1 = M_inv + (size_t)p * 256 + r1 * 16;
        float a0 = 0.0f, a1 = 0.0f;
#pragma unroll
        for (int j = 0; j < 16; j++) {
            a0 = fmaf(M0[j], pmv[j], a0);
            a1 = fmaf(M1[j], pmv[j], a1);
        }
        mu_o[(size_t)p * 16 + q]  = mu[(size_t)p * 16 + q]  + ((float)NSTEPS * DT) * a0;
        mu_o[(size_t)p * 16 + r1] = mu[(size_t)p * 16 + r1] + ((float)NSTEPS * DT) * a1;
    }

    // ---- phi update (thread q==0 of each point) ----
    if (q == 0) {
        float px = phi[p * 3 + 0], py = phi[p * 3 + 1], pz = phi[p * 3 + 2];
        const float vx = pi_phi[p * 3 + 0];
        const float vy = pi_phi[p * 3 + 1];
        const float vz = pi_phi[p * 3 + 2];
        const float TWO_PI = 6.283185307179586f;
        const float PI_F = 3.141592653589793f;
        const float R_MAX = 3.131592653589793f;
#pragma unroll 1
        for (int s = 0; s < NSTEPS; s++) {
            px += DT * vx; py += DT * vy; pz += DT * vz;
            float th = sqrtf(px * px + py * py + pz * pz);
            float ths = fmaxf(th, 1e-12f);
            float inv = 1.0f / ths;
            float ax = px * inv, ay = py * inv, az = pz * inv;
            float tw = fmodf(th, TWO_PI);
            bool flip = tw > PI_F;
            float tf = flip ? (TWO_PI - tw) : tw;
            if (flip) { ax = -ax; ay = -ay; az = -az; }
            tf = fminf(tf, R_MAX);
            px = ax * tf; py = ay * tf; pz = az * tf;
        }
        phi_o[p * 3 + 0] = px;
        phi_o[p * 3 + 1] = py;
        phi_o[p * 3 + 2] = pz;
    }
    __syncwarp();  // S0 stash visible to all threads of the point

    mm2z<16>(W0, W1, G0, G1, Ss);                // W = P * S0

#pragma unroll 1
    for (int step = 0; step < NSTEPS; step++) {
        // ===== kick1: W <- W - dt*W^2 =====
        put2(tile, q, W0, W1);                   // tile <- W
#pragma unroll
        for (int j = 0; j < 16; j++) { T0[j] = -DT * W0[j]; T1[j] = -DT * W1[j]; }
        mm2a<TSTR>(W0, W1, T0, T1, tile);        // W += (-dt*W)*W

        // ===== E = exp(2dt*W) = (Taylor4(dt*W))^2 =====
#pragma unroll
        for (int j = 0; j < 16; j++) { T0[j] = DT * W0[j]; T1[j] = DT * W1[j]; }
        put2(tile, q, T0, T1);                   // tile <- Y = dt*W
        mm2z<TSTR>(G0, G1, T0, T1, tile);        // G = Y^2
        // U = 0.5 I + (1/6) Y + (1/24) Y^2
#pragma unroll
        for (int j = 0; j < 16; j++) {
            T0[j] = fmaf(1.0f / 24.0f, G0[j], (1.0f / 6.0f) * T0[j]);
            T1[j] = fmaf(1.0f / 24.0f, G1[j], (1.0f / 6.0f) * T1[j]);
        }
        T0[q] += 0.5f; T1[r1] += 0.5f;
        put2(tile, q, T0, T1);                   // tile <- U
        // T = A0 = I + dt*W ; E4 = A0 + Y^2 * U
#pragma unroll
        for (int j = 0; j < 16; j++) { T0[j] = DT * W0[j]; T1[j] = DT * W1[j]; }
        T0[q] += 1.0f; T1[r1] += 1.0f;
        mm2a<TSTR>(T0, T1, G0, G1, tile);        // T = E4
        put2(tile, q, T0, T1);                   // tile <- E4
        mm2z<TSTR>(G0, G1, T0, T1, tile);        // G = E = E4^2
        put2(tile, q, G0, G1);                   // tile <- E

        if (step < NSTEPS - 1) {
            mm2z<TSTR>(T0, T1, W0, W1, tile);    // T = W*E  (new W)
        }

        // ===== F <- F*E  (F = E on first step) =====
        if (step == 0) {
            st_row16(Fs + q * 16, G0);           // own rows only
            st_row16(Fs + r1 * 16, G1);
        } else {
            ld_row16(G0, Fs + q * 16);           // G = F rows (own rows)
            ld_row16(G1, Fs + r1 * 16);
            mm2z<TSTR>(W0, W1, G0, G1, tile);    // W-slot = F*E
            st_row16(Fs + q * 16, W0);
            st_row16(Fs + r1 * 16, W1);
        }

        if (step < NSTEPS - 1) {
#pragma unroll
            for (int j = 0; j < 16; j++) { W0[j] = T0[j]; W1[j] = T1[j]; }
            // ===== kick2: W <- W - dt*W^2 =====
            put2(tile, q, W0, W1);
#pragma unroll
            for (int j = 0; j < 16; j++) { T0[j] = -DT * W0[j]; T1[j] = -DT * W1[j]; }
            mm2a<TSTR>(W0, W1, T0, T1, tile);
        }
    }

    // ---- final: S_new = S0 * F, symmetrize, store ----
    ld_row16(T0, Ss + q * 16);                   // T = S0 rows (own rows)
    ld_row16(T1, Ss + r1 * 16);
    __syncwarp();                                // all F rows written
    mm2z<16>(G0, G1, T0, T1, Fs);                // G = S0 * F
    __syncwarp();
    st_row16(Ss + q * 16, G0);                   // reuse Ss for transpose
    st_row16(Ss + r1 * 16, G1);
    __syncwarp();
#pragma unroll
    for (int j = 0; j < 16; j++) {
        G0[j] = 0.5f * (G0[j] + Ss[j * 16 + q]);
        G1[j] = 0.5f * (G1[j] + Ss[j * 16 + r1]);
    }
    st_row16(Sig_o + (size_t)p * 256 + q * 16, G0);
    st_row16(Sig_o + (size_t)p * 256 + r1 * 16, G1);
}

extern "C" void kernel_launch(void* const* d_in, const int* in_sizes, int n_in,
                              void* d_out, int out_size) {
    const float* mu       = (const float*)d_in[0];
    const float* Sigma    = (const float*)d_in[1];
    const float* phi      = (const float*)d_in[2];
    const float* pi_mu    = (const float*)d_in[3];
    const float* pi_Sigma = (const float*)d_in[4];
    const float* pi_phi   = (const float*)d_in[5];
    const float* M_inv    = (const float*)d_in[6];

    const int npts = in_sizes[0] / 16;  // B*N = 32768
    float* out = (float*)d_out;
    float* mu_o  = out;
    float* Sig_o = out + (size_t)npts * 16;
    float* phi_o = out + (size_t)npts * 16 + (size_t)npts * 256;

    cudaFuncSetAttribute(ham_kernel, cudaFuncAttributeMaxDynamicSharedMemorySize,
                         SMEM_BYTES);

    dim3 grid(npts / PTS);
    dim3 block(NTHREADS);
    ham_kernel<<<grid, block, SMEM_BYTES>>>(mu, Sigma, phi, pi_mu, pi_Sigma,
                                            pi_phi, M_inv, mu_o, Sig_o, phi_o);
}

// round 9
// speedup vs baseline: 1.0727x; 1.0727x over previous
#include <cuda_runtime.h>
#include <math.h>

#define DT 0.05f
#define NSTEPS 4
#define NTHREADS 256
#define PTS 32          // points per block (8 threads each)
#define TSTR 20         // tile row stride (floats): conflict-free, 16B aligned
#define PPB 836         // floats per point (mod 32 == 4 -> bank stagger)
#define TILE_OFF 0      // 320 floats: broadcast B-operand tile
#define W_OFF 320       // 256 floats: W stash (own rows), final transpose buf
#define F_OFF 576       // 256 floats: S0 initially, then F accumulator
#define SMEM_BYTES (PTS * PPB * 4)

typedef unsigned long long u64;

__device__ __forceinline__ u64 pack2(float x, float y) {
    u64 r;
    asm("mov.b64 %0, {%1, %2};" : "=l"(r) : "f"(x), "f"(y));
    return r;
}
__device__ __forceinline__ void unpack2(u64 v, float& x, float& y) {
    asm("mov.b64 {%0, %1}, %2;" : "=f"(x), "=f"(y) : "l"(v));
}
__device__ __forceinline__ void fma2(u64& d, u64 a, u64 b) {
    asm("fma.rn.f32x2 %0, %1, %2, %0;" : "+l"(d) : "l"(a), "l"(b));
}

// Write this thread's two rows (q, q+8) into the stride-TSTR tile.
__device__ __forceinline__ void put2(float* tile, int q, const float v0[16],
                                     const float v1[16]) {
    __syncwarp();
    float4* d0 = (float4*)(tile + q * TSTR);
    float4* d1 = (float4*)(tile + (q + 8) * TSTR);
    d0[0] = make_float4(v0[0], v0[1], v0[2], v0[3]);
    d0[1] = make_float4(v0[4], v0[5], v0[6], v0[7]);
    d0[2] = make_float4(v0[8], v0[9], v0[10], v0[11]);
    d0[3] = make_float4(v0[12], v0[13], v0[14], v0[15]);
    d1[0] = make_float4(v1[0], v1[1], v1[2], v1[3]);
    d1[1] = make_float4(v1[4], v1[5], v1[6], v1[7]);
    d1[2] = make_float4(v1[8], v1[9], v1[10], v1[11]);
    d1[3] = make_float4(v1[12], v1[13], v1[14], v1[15]);
    __syncwarp();
}

#define MM_BODY(BSTR)                                                        \
    _Pragma("unroll")                                                        \
    for (int k = 0; k < 16; k++) {                                           \
        const ulonglong2* bp = (const ulonglong2*)(Bs + k * (BSTR));         \
        ulonglong2 ba = bp[0], bb = bp[1], bc = bp[2], bd = bp[3];           \
        u64 ak0 = pack2(a0[k], a0[k]);                                       \
        u64 ak1 = pack2(a1[k], a1[k]);                                       \
        fma2(acc0[0], ak0, ba.x); fma2(acc0[1], ak0, ba.y);                  \
        fma2(acc0[2], ak0, bb.x); fma2(acc0[3], ak0, bb.y);                  \
        fma2(acc0[4], ak0, bc.x); fma2(acc0[5], ak0, bc.y);                  \
        fma2(acc0[6], ak0, bd.x); fma2(acc0[7], ak0, bd.y);                  \
        fma2(acc1[0], ak1, ba.x); fma2(acc1[1], ak1, ba.y);                  \
        fma2(acc1[2], ak1, bb.x); fma2(acc1[3], ak1, bb.y);                  \
        fma2(acc1[4], ak1, bc.x); fma2(acc1[5], ak1, bc.y);                  \
        fma2(acc1[6], ak1, bd.x); fma2(acc1[7], ak1, bd.y);                  \
    }

// c{0,1} = a{0,1} * B   (zero-init; c may alias a)
template <int BSTR>
__device__ __forceinline__ void mm2z(float c0[16], float c1[16],
                                     const float a0[16], const float a1[16],
                                     const float* Bs) {
    u64 acc0[8], acc1[8];
#pragma unroll
    for (int i = 0; i < 8; i++) { acc0[i] = 0ULL; acc1[i] = 0ULL; }
    MM_BODY(BSTR)
#pragma unroll
    for (int i = 0; i < 8; i++) {
        unpack2(acc0[i], c0[2 * i], c0[2 * i + 1]);
        unpack2(acc1[i], c1[2 * i], c1[2 * i + 1]);
    }
}

// c{0,1} += a{0,1} * B
template <int BSTR>
__device__ __forceinline__ void mm2a(float c0[16], float c1[16],
                                     const float a0[16], const float a1[16],
                                     const float* Bs) {
    u64 acc0[8], acc1[8];
#pragma unroll
    for (int i = 0; i < 8; i++) {
        acc0[i] = pack2(c0[2 * i], c0[2 * i + 1]);
        acc1[i] = pack2(c1[2 * i], c1[2 * i + 1]);
    }
    MM_BODY(BSTR)
#pragma unroll
    for (int i = 0; i < 8; i++) {
        unpack2(acc0[i], c0[2 * i], c0[2 * i + 1]);
        unpack2(acc1[i], c1[2 * i], c1[2 * i + 1]);
    }
}

__device__ __forceinline__ void ld_row16(float v[16], const float* src) {
    const float4* s = (const float4*)src;
#pragma unroll
    for (int i = 0; i < 4; i++) {
        float4 t = s[i];
        v[4 * i + 0] = t.x; v[4 * i + 1] = t.y;
        v[4 * i + 2] = t.z; v[4 * i + 3] = t.w;
    }
}
__device__ __forceinline__ void st_row16(float* dst, const float v[16]) {
    float4* d = (float4*)dst;
    d[0] = make_float4(v[0], v[1], v[2], v[3]);
    d[1] = make_float4(v[4], v[5], v[6], v[7]);
    d[2] = make_float4(v[8], v[9], v[10], v[11]);
    d[3] = make_float4(v[12], v[13], v[14], v[15]);
}

__global__ void __launch_bounds__(NTHREADS, 2)
ham_kernel(const float* __restrict__ mu, const float* __restrict__ Sigma,
           const float* __restrict__ phi, const float* __restrict__ pi_mu,
           const float* __restrict__ pi_Sigma, const float* __restrict__ pi_phi,
           const float* __restrict__ M_inv,
           float* __restrict__ mu_o, float* __restrict__ Sig_o,
           float* __restrict__ phi_o) {
    extern __shared__ float smem[];
    const int tid = threadIdx.x;
    const int lp = tid >> 3;   // local point 0..31
    const int q = tid & 7;     // owns rows q and q+8
    const int r1 = q + 8;
    const int p = blockIdx.x * PTS + lp;
    float* tile = smem + lp * PPB + TILE_OFF;
    float* Ws = smem + lp * PPB + W_OFF;   // stride 16
    float* Fs = smem + lp * PPB + F_OFF;   // stride 16

    // Exactly TWO register row-pairs: W and A (64 floats) + mm accumulator.
    float W0[16], W1[16], A0[16], A1[16];

    // ---- S0 -> Fs (temporary home); P -> A ----
    ld_row16(A0, Sigma + (size_t)p * 256 + q * 16);
    ld_row16(A1, Sigma + (size_t)p * 256 + r1 * 16);
    st_row16(Fs + q * 16, A0);
    st_row16(Fs + r1 * 16, A1);
    ld_row16(A0, pi_Sigma + (size_t)p * 256 + q * 16);
    ld_row16(A1, pi_Sigma + (size_t)p * 256 + r1 * 16);

    // ---- mu update (rows q, q+8): mu + NSTEPS*dt * M_inv @ pi_mu ----
    {
        float pmv[16];
        ld_row16(pmv, pi_mu + (size_t)p * 16);
        const float* M0 = M_inv + (size_t)p * 256 + q * 16;
        const float* M1 = M_inv + (size_t)p * 256 + r1 * 16;
        float s0 = 0.0f, s1 = 0.0f;
#pragma unroll
        for (int j = 0; j < 16; j++) {
            s0 = fmaf(M0[j], pmv[j], s0);
            s1 = fmaf(M1[j], pmv[j], s1);
        }
        mu_o[(size_t)p * 16 + q]  = mu[(size_t)p * 16 + q]  + ((float)NSTEPS * DT) * s0;
        mu_o[(size_t)p * 16 + r1] = mu[(size_t)p * 16 + r1] + ((float)NSTEPS * DT) * s1;
    }

    // ---- phi update (thread q==0 of each point) ----
    if (q == 0) {
        float px = phi[p * 3 + 0], py = phi[p * 3 + 1], pz = phi[p * 3 + 2];
        const float vx = pi_phi[p * 3 + 0];
        const float vy = pi_phi[p * 3 + 1];
        const float vz = pi_phi[p * 3 + 2];
        const float TWO_PI = 6.283185307179586f;
        const float PI_F = 3.141592653589793f;
        const float R_MAX = 3.131592653589793f;
#pragma unroll 1
        for (int s = 0; s < NSTEPS; s++) {
            px += DT * vx; py += DT * vy; pz += DT * vz;
            float th = sqrtf(px * px + py * py + pz * pz);
            float ths = fmaxf(th, 1e-12f);
            float inv = 1.0f / ths;
            float ax = px * inv, ay = py * inv, az = pz * inv;
            float tw = fmodf(th, TWO_PI);
            bool flip = tw > PI_F;
            float tf = flip ? (TWO_PI - tw) : tw;
            if (flip) { ax = -ax; ay = -ay; az = -az; }
            tf = fminf(tf, R_MAX);
            px = ax * tf; py = ay * tf; pz = az * tf;
        }
        phi_o[p * 3 + 0] = px;
        phi_o[p * 3 + 1] = py;
        phi_o[p * 3 + 2] = pz;
    }
    __syncwarp();  // S0 (in Fs) visible to all threads of the point

    mm2z<16>(W0, W1, A0, A1, Fs);                // W = P * S0

#pragma unroll 1
    for (int step = 0; step < NSTEPS; step++) {
        // ===== kick1: W <- W - dt*W^2 =====
        put2(tile, q, W0, W1);                   // tile <- W
#pragma unroll
        for (int j = 0; j < 16; j++) { A0[j] = -DT * W0[j]; A1[j] = -DT * W1[j]; }
        mm2a<TSTR>(W0, W1, A0, A1, tile);        // W += (-dt*W)*W_old

        // ===== E = exp(2dt*W) = (Taylor4(dt*W))^2 =====
        st_row16(Ws + q * 16, W0);               // stash W (own rows)
        st_row16(Ws + r1 * 16, W1);
#pragma unroll
        for (int j = 0; j < 16; j++) { A0[j] = DT * W0[j]; A1[j] = DT * W1[j]; }
        put2(tile, q, A0, A1);                   // tile <- Y = dt*W
        mm2z<TSTR>(W0, W1, A0, A1, tile);        // W-regs <- Y^2
        // A <- U = 0.5 I + (1/6) Y + (1/24) Y^2
#pragma unroll
        for (int j = 0; j < 16; j++) {
            A0[j] = fmaf(1.0f / 24.0f, W0[j], (1.0f / 6.0f) * A0[j]);
            A1[j] = fmaf(1.0f / 24.0f, W1[j], (1.0f / 6.0f) * A1[j]);
        }
        A0[q] += 0.5f; A1[r1] += 0.5f;
        put2(tile, q, A0, A1);                   // tile <- U
        // A <- A0term = I + dt*W  (reload W from stash)
        ld_row16(A0, Ws + q * 16);
        ld_row16(A1, Ws + r1 * 16);
#pragma unroll
        for (int j = 0; j < 16; j++) { A0[j] *= DT; A1[j] *= DT; }
        A0[q] += 1.0f; A1[r1] += 1.0f;
        mm2a<TSTR>(A0, A1, W0, W1, tile);        // A = A0term + Y^2*U = E4
        put2(tile, q, A0, A1);                   // tile <- E4
        mm2z<TSTR>(A0, A1, A0, A1, tile);        // A <- E4^2 = E
        put2(tile, q, A0, A1);                   // tile <- E  (stays for 3 mms)

        // ===== F <- F*E  (F := E on first step; clobbers W regs) =====
        if (step == 0) {
            st_row16(Fs + q * 16, A0);           // own rows only
            st_row16(Fs + r1 * 16, A1);
        } else {
            ld_row16(W0, Fs + q * 16);           // own rows
            ld_row16(W1, Fs + r1 * 16);
            mm2z<TSTR>(W0, W1, W0, W1, tile);    // W-regs <- F*E
            st_row16(Fs + q * 16, W0);
            st_row16(Fs + r1 * 16, W1);
        }

        // ===== W <- W*E, then kick2 (both dead on last step) =====
        if (step < NSTEPS - 1) {
            ld_row16(W0, Ws + q * 16);           // own rows
            ld_row16(W1, Ws + r1 * 16);
            mm2z<TSTR>(W0, W1, W0, W1, tile);    // W <- W_old*E
            // kick2: W <- W - dt*W^2
            put2(tile, q, W0, W1);
#pragma unroll
            for (int j = 0; j < 16; j++) { A0[j] = -DT * W0[j]; A1[j] = -DT * W1[j]; }
            mm2a<TSTR>(W0, W1, A0, A1, tile);
        }
    }

    // ---- final: S_new = S0 * F (S0 rows re-read from gmem/L2) ----
    ld_row16(A0, Sigma + (size_t)p * 256 + q * 16);
    ld_row16(A1, Sigma + (size_t)p * 256 + r1 * 16);
    __syncwarp();                                // all F rows written
    mm2z<16>(W0, W1, A0, A1, Fs);                // W = S0 * F
    __syncwarp();
    st_row16(Ws + q * 16, W0);                   // Ws reused for transpose
    st_row16(Ws + r1 * 16, W1);
    __syncwarp();
#pragma unroll
    for (int j = 0; j < 16; j++) {
        W0[j] = 0.5f * (W0[j] + Ws[j * 16 + q]);
        W1[j] = 0.5f * (W1[j] + Ws[j * 16 + r1]);
    }
    st_row16(Sig_o + (size_t)p * 256 + q * 16, W0);
    st_row16(Sig_o + (size_t)p * 256 + r1 * 16, W1);
}

extern "C" void kernel_launch(void* const* d_in, const int* in_sizes, int n_in,
                              void* d_out, int out_size) {
    const float* mu       = (const float*)d_in[0];
    const float* Sigma    = (const float*)d_in[1];
    const float* phi      = (const float*)d_in[2];
    const float* pi_mu    = (const float*)d_in[3];
    const float* pi_Sigma = (const float*)d_in[4];
    const float* pi_phi   = (const float*)d_in[5];
    const float* M_inv    = (const float*)d_in[6];

    const int npts = in_sizes[0] / 16;  // B*N = 32768
    float* out = (float*)d_out;
    float* mu_o  = out;
    float* Sig_o = out + (size_t)npts * 16;
    float* phi_o = out + (size_t)npts * 16 + (size_t)npts * 256;

    cudaFuncSetAttribute(ham_kernel, cudaFuncAttributeMaxDynamicSharedMemorySize,
                         SMEM_BYTES);

    dim3 grid(npts / PTS);
    dim3 block(NTHREADS);
    ham_kernel<<<grid, block, SMEM_BYTES>>>(mu, Sigma, phi, pi_mu, pi_Sigma,
                                            pi_phi, M_inv, mu_o, Sig_o, phi_o);
}

// round 10
// speedup vs baseline: 1.0827x; 1.0094x over previous
#include <cuda_runtime.h>
#include <math.h>

#define DT 0.05f
#define NSTEPS 4
#define NTHREADS 256
#define PTS 32          // points per block (8 threads each)
#define TSTR 20         // tile row stride (floats): conflict-free, 16B aligned
#define PPB 836         // floats per point (mod 32 == 4 -> bank stagger)
#define TILE_OFF 0      // 320 floats: broadcast B-operand tile
#define W_OFF 320       // 256 floats: W stash (own rows), final transpose buf
#define F_OFF 576       // 256 floats: S0 initially, then F accumulator
#define SMEM_BYTES (PTS * PPB * 4)

typedef unsigned long long u64;

__device__ __forceinline__ u64 pack2(float x, float y) {
    u64 r;
    asm("mov.b64 %0, {%1, %2};" : "=l"(r) : "f"(x), "f"(y));
    return r;
}
__device__ __forceinline__ void unpack2(u64 v, float& x, float& y) {
    asm("mov.b64 {%0, %1}, %2;" : "=f"(x), "=f"(y) : "l"(v));
}
__device__ __forceinline__ void fma2(u64& d, u64 a, u64 b) {
    asm("fma.rn.f32x2 %0, %1, %2, %0;" : "+l"(d) : "l"(a), "l"(b));
}

// Write this thread's two rows (q, q+8) into the stride-TSTR tile.
__device__ __forceinline__ void put2(float* tile, int q, const float v0[16],
                                     const float v1[16]) {
    __syncwarp();
    float4* d0 = (float4*)(tile + q * TSTR);
    float4* d1 = (float4*)(tile + (q + 8) * TSTR);
    d0[0] = make_float4(v0[0], v0[1], v0[2], v0[3]);
    d0[1] = make_float4(v0[4], v0[5], v0[6], v0[7]);
    d0[2] = make_float4(v0[8], v0[9], v0[10], v0[11]);
    d0[3] = make_float4(v0[12], v0[13], v0[14], v0[15]);
    d1[0] = make_float4(v1[0], v1[1], v1[2], v1[3]);
    d1[1] = make_float4(v1[4], v1[5], v1[6], v1[7]);
    d1[2] = make_float4(v1[8], v1[9], v1[10], v1[11]);
    d1[3] = make_float4(v1[12], v1[13], v1[14], v1[15]);
    __syncwarp();
}

// c{0,1} = a{0,1} * B   (zero-init; c may alias a). Literal #pragma unroll —
// a rolled k-loop would demote the register arrays to local memory (R8/R9 bug).
template <int BSTR>
__device__ __forceinline__ void mm2z(float c0[16], float c1[16],
                                     const float a0[16], const float a1[16],
                                     const float* Bs) {
    u64 acc0[8], acc1[8];
#pragma unroll
    for (int i = 0; i < 8; i++) { acc0[i] = 0ULL; acc1[i] = 0ULL; }
#pragma unroll
    for (int k = 0; k < 16; k++) {
        const ulonglong2* bp = (const ulonglong2*)(Bs + k * BSTR);
        ulonglong2 ba = bp[0], bb = bp[1], bc = bp[2], bd = bp[3];
        u64 ak0 = pack2(a0[k], a0[k]);
        u64 ak1 = pack2(a1[k], a1[k]);
        fma2(acc0[0], ak0, ba.x); fma2(acc0[1], ak0, ba.y);
        fma2(acc0[2], ak0, bb.x); fma2(acc0[3], ak0, bb.y);
        fma2(acc0[4], ak0, bc.x); fma2(acc0[5], ak0, bc.y);
        fma2(acc0[6], ak0, bd.x); fma2(acc0[7], ak0, bd.y);
        fma2(acc1[0], ak1, ba.x); fma2(acc1[1], ak1, ba.y);
        fma2(acc1[2], ak1, bb.x); fma2(acc1[3], ak1, bb.y);
        fma2(acc1[4], ak1, bc.x); fma2(acc1[5], ak1, bc.y);
        fma2(acc1[6], ak1, bd.x); fma2(acc1[7], ak1, bd.y);
    }
#pragma unroll
    for (int i = 0; i < 8; i++) {
        unpack2(acc0[i], c0[2 * i], c0[2 * i + 1]);
        unpack2(acc1[i], c1[2 * i], c1[2 * i + 1]);
    }
}

// c{0,1} += a{0,1} * B
template <int BSTR>
__device__ __forceinline__ void mm2a(float c0[16], float c1[16],
                                     const float a0[16], const float a1[16],
                                     const float* Bs) {
    u64 acc0[8], acc1[8];
#pragma unroll
    for (int i = 0; i < 8; i++) {
        acc0[i] = pack2(c0[2 * i], c0[2 * i + 1]);
        acc1[i] = pack2(c1[2 * i], c1[2 * i + 1]);
    }
#pragma unroll
    for (int k = 0; k < 16; k++) {
        const ulonglong2* bp = (const ulonglong2*)(Bs + k * BSTR);
        ulonglong2 ba = bp[0], bb = bp[1], bc = bp[2], bd = bp[3];
        u64 ak0 = pack2(a0[k], a0[k]);
        u64 ak1 = pack2(a1[k], a1[k]);
        fma2(acc0[0], ak0, ba.x); fma2(acc0[1], ak0, ba.y);
        fma2(acc0[2], ak0, bb.x); fma2(acc0[3], ak0, bb.y);
        fma2(acc0[4], ak0, bc.x); fma2(acc0[5], ak0, bc.y);
        fma2(acc0[6], ak0, bd.x); fma2(acc0[7], ak0, bd.y);
        fma2(acc1[0], ak1, ba.x); fma2(acc1[1], ak1, ba.y);
        fma2(acc1[2], ak1, bb.x); fma2(acc1[3], ak1, bb.y);
        fma2(acc1[4], ak1, bc.x); fma2(acc1[5], ak1, bc.y);
        fma2(acc1[6], ak1, bd.x); fma2(acc1[7], ak1, bd.y);
    }
#pragma unroll
    for (int i = 0; i < 8; i++) {
        unpack2(acc0[i], c0[2 * i], c0[2 * i + 1]);
        unpack2(acc1[i], c1[2 * i], c1[2 * i + 1]);
    }
}

__device__ __forceinline__ void ld_row16(float v[16], const float* src) {
    const float4* s = (const float4*)src;
#pragma unroll
    for (int i = 0; i < 4; i++) {
        float4 t = s[i];
        v[4 * i + 0] = t.x; v[4 * i + 1] = t.y;
        v[4 * i + 2] = t.z; v[4 * i + 3] = t.w;
    }
}
__device__ __forceinline__ void st_row16(float* dst, const float v[16]) {
    float4* d = (float4*)dst;
    d[0] = make_float4(v[0], v[1], v[2], v[3]);
    d[1] = make_float4(v[4], v[5], v[6], v[7]);
    d[2] = make_float4(v[8], v[9], v[10], v[11]);
    d[3] = make_float4(v[12], v[13], v[14], v[15]);
}

__global__ void __launch_bounds__(NTHREADS, 2)
ham_kernel(const float* __restrict__ mu, const float* __restrict__ Sigma,
           const float* __restrict__ phi, const float* __restrict__ pi_mu,
           const float* __restrict__ pi_Sigma, const float* __restrict__ pi_phi,
           const float* __restrict__ M_inv,
           float* __restrict__ mu_o, float* __restrict__ Sig_o,
           float* __restrict__ phi_o) {
    extern __shared__ float smem[];
    const int tid = threadIdx.x;
    const int lp = tid >> 3;   // local point 0..31
    const int q = tid & 7;     // owns rows q and q+8
    const int r1 = q + 8;
    const int p = blockIdx.x * PTS + lp;
    float* tile = smem + lp * PPB + TILE_OFF;
    float* Ws = smem + lp * PPB + W_OFF;   // stride 16
    float* Fs = smem + lp * PPB + F_OFF;   // stride 16

    // Exactly TWO register row-pairs: W and A (64 floats) + mm accumulator.
    float W0[16], W1[16], A0[16], A1[16];

    // ---- S0 -> Fs (temporary home); P -> A ----
    ld_row16(A0, Sigma + (size_t)p * 256 + q * 16);
    ld_row16(A1, Sigma + (size_t)p * 256 + r1 * 16);
    st_row16(Fs + q * 16, A0);
    st_row16(Fs + r1 * 16, A1);
    ld_row16(A0, pi_Sigma + (size_t)p * 256 + q * 16);
    ld_row16(A1, pi_Sigma + (size_t)p * 256 + r1 * 16);

    // ---- mu update (rows q, q+8): mu + NSTEPS*dt * M_inv @ pi_mu ----
    {
        float pmv[16];
        ld_row16(pmv, pi_mu + (size_t)p * 16);
        const float* M0 = M_inv + (size_t)p * 256 + q * 16;
        const float* M1 = M_inv + (size_t)p * 256 + r1 * 16;
        float s0 = 0.0f, s1 = 0.0f;
#pragma unroll
        for (int j = 0; j < 16; j++) {
            s0 = fmaf(M0[j], pmv[j], s0);
            s1 = fmaf(M1[j], pmv[j], s1);
        }
        mu_o[(size_t)p * 16 + q]  = mu[(size_t)p * 16 + q]  + ((float)NSTEPS * DT) * s0;
        mu_o[(size_t)p * 16 + r1] = mu[(size_t)p * 16 + r1] + ((float)NSTEPS * DT) * s1;
    }

    // ---- phi update (thread q==0 of each point) ----
    if (q == 0) {
        float px = phi[p * 3 + 0], py = phi[p * 3 + 1], pz = phi[p * 3 + 2];
        const float vx = pi_phi[p * 3 + 0];
        const float vy = pi_phi[p * 3 + 1];
        const float vz = pi_phi[p * 3 + 2];
        const float TWO_PI = 6.283185307179586f;
        const float PI_F = 3.141592653589793f;
        const float R_MAX = 3.131592653589793f;
#pragma unroll 1
        for (int s = 0; s < NSTEPS; s++) {
            px += DT * vx; py += DT * vy; pz += DT * vz;
            float th = sqrtf(px * px + py * py + pz * pz);
            float ths = fmaxf(th, 1e-12f);
            float inv = 1.0f / ths;
            float ax = px * inv, ay = py * inv, az = pz * inv;
            float tw = fmodf(th, TWO_PI);
            bool flip = tw > PI_F;
            float tf = flip ? (TWO_PI - tw) : tw;
            if (flip) { ax = -ax; ay = -ay; az = -az; }
            tf = fminf(tf, R_MAX);
            px = ax * tf; py = ay * tf; pz = az * tf;
        }
        phi_o[p * 3 + 0] = px;
        phi_o[p * 3 + 1] = py;
        phi_o[p * 3 + 2] = pz;
    }
    __syncwarp();  // S0 (in Fs) visible to all threads of the point

    mm2z<16>(W0, W1, A0, A1, Fs);                // W = P * S0

#pragma unroll 1
    for (int step = 0; step < NSTEPS; step++) {
        // ===== kick1: W <- W - dt*W^2 =====
        put2(tile, q, W0, W1);                   // tile <- W
#pragma unroll
        for (int j = 0; j < 16; j++) { A0[j] = -DT * W0[j]; A1[j] = -DT * W1[j]; }
        mm2a<TSTR>(W0, W1, A0, A1, tile);        // W += (-dt*W)*W_old

        // ===== E = exp(2dt*W) = (Taylor4(dt*W))^2 =====
        st_row16(Ws + q * 16, W0);               // stash W (own rows)
        st_row16(Ws + r1 * 16, W1);
#pragma unroll
        for (int j = 0; j < 16; j++) { A0[j] = DT * W0[j]; A1[j] = DT * W1[j]; }
        put2(tile, q, A0, A1);                   // tile <- Y = dt*W
        mm2z<TSTR>(W0, W1, A0, A1, tile);        // W-regs <- Y^2
        // A <- U = 0.5 I + (1/6) Y + (1/24) Y^2
#pragma unroll
        for (int j = 0; j < 16; j++) {
            A0[j] = fmaf(1.0f / 24.0f, W0[j], (1.0f / 6.0f) * A0[j]);
            A1[j] = fmaf(1.0f / 24.0f, W1[j], (1.0f / 6.0f) * A1[j]);
        }
        A0[q] += 0.5f; A1[r1] += 0.5f;
        put2(tile, q, A0, A1);                   // tile <- U
        // A <- I + dt*W  (reload W from stash)
        ld_row16(A0, Ws + q * 16);
        ld_row16(A1, Ws + r1 * 16);
#pragma unroll
        for (int j = 0; j < 16; j++) { A0[j] *= DT; A1[j] *= DT; }
        A0[q] += 1.0f; A1[r1] += 1.0f;
        mm2a<TSTR>(A0, A1, W0, W1, tile);        // A = (I+dtW) + Y^2*U = E4
        put2(tile, q, A0, A1);                   // tile <- E4
        mm2z<TSTR>(A0, A1, A0, A1, tile);        // A <- E4^2 = E
        put2(tile, q, A0, A1);                   // tile <- E  (stays for 3 mms)

        // ===== F <- F*E  (F := E on first step; clobbers W regs) =====
        if (step == 0) {
            st_row16(Fs + q * 16, A0);           // own rows only
            st_row16(Fs + r1 * 16, A1);
        } else {
            ld_row16(W0, Fs + q * 16);           // own rows
            ld_row16(W1, Fs + r1 * 16);
            mm2z<TSTR>(W0, W1, W0, W1, tile);    // W-regs <- F*E
            st_row16(Fs + q * 16, W0);
            st_row16(Fs + r1 * 16, W1);
        }

        // ===== W <- W*E, then kick2 (both dead on last step) =====
        if (step < NSTEPS - 1) {
            ld_row16(W0, Ws + q * 16);           // own rows
            ld_row16(W1, Ws + r1 * 16);
            mm2z<TSTR>(W0, W1, W0, W1, tile);    // W <- W_old*E
            // kick2: W <- W - dt*W^2
            put2(tile, q, W0, W1);
#pragma unroll
            for (int j = 0; j < 16; j++) { A0[j] = -DT * W0[j]; A1[j] = -DT * W1[j]; }
            mm2a<TSTR>(W0, W1, A0, A1, tile);
        }
    }

    // ---- final: S_new = S0 * F (S0 rows re-read from gmem/L2) ----
    ld_row16(A0, Sigma + (size_t)p * 256 + q * 16);
    ld_row16(A1, Sigma + (size_t)p * 256 + r1 * 16);
    __syncwarp();                                // all F rows written
    mm2z<16>(W0, W1, A0, A1, Fs);                // W = S0 * F
    __syncwarp();
    st_row16(Ws + q * 16, W0);                   // Ws reused for transpose
    st_row16(Ws + r1 * 16, W1);
    __syncwarp();
#pragma unroll
    for (int j = 0; j < 16; j++) {
        W0[j] = 0.5f * (W0[j] + Ws[j * 16 + q]);
        W1[j] = 0.5f * (W1[j] + Ws[j * 16 + r1]);
    }
    st_row16(Sig_o + (size_t)p * 256 + q * 16, W0);
    st_row16(Sig_o + (size_t)p * 256 + r1 * 16, W1);
}

extern "C" void kernel_launch(void* const* d_in, const int* in_sizes, int n_in,
                              void* d_out, int out_size) {
    const float* mu       = (const float*)d_in[0];
    const float* Sigma    = (const float*)d_in[1];
    const float* phi      = (const float*)d_in[2];
    const float* pi_mu    = (const float*)d_in[3];
    const float* pi_Sigma = (const float*)d_in[4];
    const float* pi_phi   = (const float*)d_in[5];
    const float* M_inv    = (const float*)d_in[6];

    const int npts = in_sizes[0] / 16;  // B*N = 32768
    float* out = (float*)d_out;
    float* mu_o  = out;
    float* Sig_o = out + (size_t)npts * 16;
    float* phi_o = out + (size_t)npts * 16 + (size_t)npts * 256;

    cudaFuncSetAttribute(ham_kernel, cudaFuncAttributeMaxDynamicSharedMemorySize,
                         SMEM_BYTES);

    dim3 grid(npts / PTS);
    dim3 block(NTHREADS);
    ham_kernel<<<grid, block, SMEM_BYTES>>>(mu, Sigma, phi, pi_mu, pi_Sigma,
                                            pi_phi, M_inv, mu_o, Sig_o, phi_o);
}

// round 11
// speedup vs baseline: 1.4050x; 1.2977x over previous
#include <cuda_runtime.h>
#include <math.h>

#define DT 0.05f
#define NSTEPS 4
#define NTHREADS 256
#define PTS 32          // points per block (8 threads each)
#define TSTR 20         // tile row stride (floats): conflict-free, 16B aligned
#define PPB 580         // floats per point: tile 320 + Fs 256 + pad (mod 32 == 4)
#define TILE_OFF 0
#define F_OFF 320       // S0 initially, then F accumulator
#define SMEM_BYTES (PTS * PPB * 4)

typedef unsigned long long u64;

__device__ __forceinline__ u64 pack2(float x, float y) {
    u64 r;
    asm("mov.b64 %0, {%1, %2};" : "=l"(r) : "f"(x), "f"(y));
    return r;
}
__device__ __forceinline__ void unpack2(u64 v, float& x, float& y) {
    asm("mov.b64 {%0, %1}, %2;" : "=f"(x), "=f"(y) : "l"(v));
}
__device__ __forceinline__ void fma2(u64& d, u64 a, u64 b) {
    asm("fma.rn.f32x2 %0, %1, %2, %0;" : "+l"(d) : "l"(a), "l"(b));
}

__device__ __forceinline__ void put2(float* tile, int q, const float v0[16],
                                     const float v1[16]) {
    __syncwarp();
    float4* d0 = (float4*)(tile + q * TSTR);
    float4* d1 = (float4*)(tile + (q + 8) * TSTR);
    d0[0] = make_float4(v0[0], v0[1], v0[2], v0[3]);
    d0[1] = make_float4(v0[4], v0[5], v0[6], v0[7]);
    d0[2] = make_float4(v0[8], v0[9], v0[10], v0[11]);
    d0[3] = make_float4(v0[12], v0[13], v0[14], v0[15]);
    d1[0] = make_float4(v1[0], v1[1], v1[2], v1[3]);
    d1[1] = make_float4(v1[4], v1[5], v1[6], v1[7]);
    d1[2] = make_float4(v1[8], v1[9], v1[10], v1[11]);
    d1[3] = make_float4(v1[12], v1[13], v1[14], v1[15]);
    __syncwarp();
}

// c{0,1} = a{0,1} * B. c and a must be DISTINCT arrays (codegen safety).
template <int BSTR>
__device__ __forceinline__ void mm2z(float c0[16], float c1[16],
                                     const float a0[16], const float a1[16],
                                     const float* Bs) {
    u64 acc0[8], acc1[8];
#pragma unroll
    for (int i = 0; i < 8; i++) { acc0[i] = 0ULL; acc1[i] = 0ULL; }
#pragma unroll
    for (int k = 0; k < 16; k++) {
        const ulonglong2* bp = (const ulonglong2*)(Bs + k * BSTR);
        ulonglong2 ba = bp[0], bb = bp[1], bc = bp[2], bd = bp[3];
        u64 ak0 = pack2(a0[k], a0[k]);
        u64 ak1 = pack2(a1[k], a1[k]);
        fma2(acc0[0], ak0, ba.x); fma2(acc0[1], ak0, ba.y);
        fma2(acc0[2], ak0, bb.x); fma2(acc0[3], ak0, bb.y);
        fma2(acc0[4], ak0, bc.x); fma2(acc0[5], ak0, bc.y);
        fma2(acc0[6], ak0, bd.x); fma2(acc0[7], ak0, bd.y);
        fma2(acc1[0], ak1, ba.x); fma2(acc1[1], ak1, ba.y);
        fma2(acc1[2], ak1, bb.x); fma2(acc1[3], ak1, bb.y);
        fma2(acc1[4], ak1, bc.x); fma2(acc1[5], ak1, bc.y);
        fma2(acc1[6], ak1, bd.x); fma2(acc1[7], ak1, bd.y);
    }
#pragma unroll
    for (int i = 0; i < 8; i++) {
        unpack2(acc0[i], c0[2 * i], c0[2 * i + 1]);
        unpack2(acc1[i], c1[2 * i], c1[2 * i + 1]);
    }
}

// c{0,1} += a{0,1} * B. c and a must be DISTINCT arrays.
template <int BSTR>
__device__ __forceinline__ void mm2a(float c0[16], float c1[16],
                                     const float a0[16], const float a1[16],
                                     const float* Bs) {
    u64 acc0[8], acc1[8];
#pragma unroll
    for (int i = 0; i < 8; i++) {
        acc0[i] = pack2(c0[2 * i], c0[2 * i + 1]);
        acc1[i] = pack2(c1[2 * i], c1[2 * i + 1]);
    }
#pragma unroll
    for (int k = 0; k < 16; k++) {
        const ulonglong2* bp = (const ulonglong2*)(Bs + k * BSTR);
        ulonglong2 ba = bp[0], bb = bp[1], bc = bp[2], bd = bp[3];
        u64 ak0 = pack2(a0[k], a0[k]);
        u64 ak1 = pack2(a1[k], a1[k]);
        fma2(acc0[0], ak0, ba.x); fma2(acc0[1], ak0, ba.y);
        fma2(acc0[2], ak0, bb.x); fma2(acc0[3], ak0, bb.y);
        fma2(acc0[4], ak0, bc.x); fma2(acc0[5], ak0, bc.y);
        fma2(acc0[6], ak0, bd.x); fma2(acc0[7], ak0, bd.y);
        fma2(acc1[0], ak1, ba.x); fma2(acc1[1], ak1, ba.y);
        fma2(acc1[2], ak1, bb.x); fma2(acc1[3], ak1, bb.y);
        fma2(acc1[4], ak1, bc.x); fma2(acc1[5], ak1, bc.y);
        fma2(acc1[6], ak1, bd.x); fma2(acc1[7], ak1, bd.y);
    }
#pragma unroll
    for (int i = 0; i < 8; i++) {
        unpack2(acc0[i], c0[2 * i], c0[2 * i + 1]);
        unpack2(acc1[i], c1[2 * i], c1[2 * i + 1]);
    }
}

__device__ __forceinline__ void ld_row16(float v[16], const float* src) {
    const float4* s = (const float4*)src;
#pragma unroll
    for (int i = 0; i < 4; i++) {
        float4 t = s[i];
        v[4 * i + 0] = t.x; v[4 * i + 1] = t.y;
        v[4 * i + 2] = t.z; v[4 * i + 3] = t.w;
    }
}
__device__ __forceinline__ void st_row16(float* dst, const float v[16]) {
    float4* d = (float4*)dst;
    d[0] = make_float4(v[0], v[1], v[2], v[3]);
    d[1] = make_float4(v[4], v[5], v[6], v[7]);
    d[2] = make_float4(v[8], v[9], v[10], v[11]);
    d[3] = make_float4(v[12], v[13], v[14], v[15]);
}

// E-section: tile <- E = (Taylor4(dt*W))^2 = exp(2dt*W) + O(||dtW||^5).
// Inputs: W (preserved). Clobbers T, G. On exit tile holds E (and G == E).
#define E_SECTION()                                                          \
    do {                                                                     \
        _Pragma("unroll")                                                    \
        for (int j = 0; j < 16; j++) { T0[j] = DT * W0[j]; T1[j] = DT * W1[j]; } \
        put2(tile, q, T0, T1);                   /* tile <- Y = dt*W */      \
        mm2z<TSTR>(G0, G1, T0, T1, tile);        /* G = Y^2 */               \
        _Pragma("unroll")                                                    \
        for (int j = 0; j < 16; j++) {                                       \
            T0[j] = fmaf(1.0f / 24.0f, G0[j], (1.0f / 6.0f) * T0[j]);        \
            T1[j] = fmaf(1.0f / 24.0f, G1[j], (1.0f / 6.0f) * T1[j]);        \
        }                                                                    \
        T0[q] += 0.5f; T1[r1] += 0.5f;                                       \
        put2(tile, q, T0, T1);                   /* tile <- U */             \
        _Pragma("unroll")                                                    \
        for (int j = 0; j < 16; j++) { T0[j] = DT * W0[j]; T1[j] = DT * W1[j]; } \
        T0[q] += 1.0f; T1[r1] += 1.0f;                                       \
        mm2a<TSTR>(T0, T1, G0, G1, tile);        /* T = E4 */                \
        put2(tile, q, T0, T1);                   /* tile <- E4 */            \
        mm2z<TSTR>(G0, G1, T0, T1, tile);        /* G = E4^2 = E */          \
        put2(tile, q, G0, G1);                   /* tile <- E */             \
    } while (0)

// kick: W <- W - dt*W^2
#define KICK()                                                               \
    do {                                                                     \
        put2(tile, q, W0, W1);                                               \
        _Pragma("unroll")                                                    \
        for (int j = 0; j < 16; j++) { T0[j] = -DT * W0[j]; T1[j] = -DT * W1[j]; } \
        mm2a<TSTR>(W0, W1, T0, T1, tile);                                    \
    } while (0)

__global__ void __launch_bounds__(NTHREADS, 2)
ham_kernel(const float* __restrict__ mu, const float* __restrict__ Sigma,
           const float* __restrict__ phi, const float* __restrict__ pi_mu,
           const float* __restrict__ pi_Sigma, const float* __restrict__ pi_phi,
           const float* __restrict__ M_inv,
           float* __restrict__ mu_o, float* __restrict__ Sig_o,
           float* __restrict__ phi_o) {
    extern __shared__ float smem[];
    const int tid = threadIdx.x;
    const int lp = tid >> 3;   // local point 0..31
    const int q = tid & 7;     // owns rows q and q+8
    const int r1 = q + 8;
    const int p = blockIdx.x * PTS + lp;
    float* tile = smem + lp * PPB + TILE_OFF;
    float* Fs = smem + lp * PPB + F_OFF;   // stride 16

    float W0[16], W1[16], T0[16], T1[16], G0[16], G1[16];

    // ---- S0 -> Fs (temporary home); P -> T ----
    ld_row16(T0, Sigma + (size_t)p * 256 + q * 16);
    ld_row16(T1, Sigma + (size_t)p * 256 + r1 * 16);
    st_row16(Fs + q * 16, T0);
    st_row16(Fs + r1 * 16, T1);
    ld_row16(T0, pi_Sigma + (size_t)p * 256 + q * 16);
    ld_row16(T1, pi_Sigma + (size_t)p * 256 + r1 * 16);

    // ---- mu update: mu + NSTEPS*dt * M_inv @ pi_mu ----
    {
        float pmv[16];
        ld_row16(pmv, pi_mu + (size_t)p * 16);
        const float* M0 = M_inv + (size_t)p * 256 + q * 16;
        const float* M1 = M_inv + (size_t)p * 256 + r1 * 16;
        float s0 = 0.0f, s1 = 0.0f;
#pragma unroll
        for (int j = 0; j < 16; j++) {
            s0 = fmaf(M0[j], pmv[j], s0);
            s1 = fmaf(M1[j], pmv[j], s1);
        }
        mu_o[(size_t)p * 16 + q]  = mu[(size_t)p * 16 + q]  + ((float)NSTEPS * DT) * s0;
        mu_o[(size_t)p * 16 + r1] = mu[(size_t)p * 16 + r1] + ((float)NSTEPS * DT) * s1;
    }

    // ---- phi update (thread q==0 of each point) ----
    if (q == 0) {
        float px = phi[p * 3 + 0], py = phi[p * 3 + 1], pz = phi[p * 3 + 2];
        const float vx = pi_phi[p * 3 + 0];
        const float vy = pi_phi[p * 3 + 1];
        const float vz = pi_phi[p * 3 + 2];
        const float TWO_PI = 6.283185307179586f;
        const float PI_F = 3.141592653589793f;
        const float R_MAX = 3.131592653589793f;
#pragma unroll 1
        for (int s = 0; s < NSTEPS; s++) {
            px += DT * vx; py += DT * vy; pz += DT * vz;
            float th = sqrtf(px * px + py * py + pz * pz);
            float ths = fmaxf(th, 1e-12f);
            float inv = 1.0f / ths;
            float ax = px * inv, ay = py * inv, az = pz * inv;
            float tw = fmodf(th, TWO_PI);
            bool flip = tw > PI_F;
            float tf = flip ? (TWO_PI - tw) : tw;
            if (flip) { ax = -ax; ay = -ay; az = -az; }
            tf = fminf(tf, R_MAX);
            px = ax * tf; py = ay * tf; pz = az * tf;
        }
        phi_o[p * 3 + 0] = px;
        phi_o[p * 3 + 1] = py;
        phi_o[p * 3 + 2] = pz;
    }
    __syncwarp();  // S0 (in Fs) visible to all threads of the point

    // ===== peel step 0: W = P*S0 ; kick ; E0 ; F := E0 =====
    mm2z<16>(W0, W1, T0, T1, Fs);                // W = P * S0
    KICK();
    E_SECTION();                                 // tile = E0, G = E0
    st_row16(Fs + q * 16, G0);                   // F := E0 (own rows)
    st_row16(Fs + r1 * 16, G1);

    // ===== steps 1..3: branch-free uniform body =====
#pragma unroll 1
    for (int step = 1; step < NSTEPS; step++) {
        // W <- W * E_{step-1}   (tile holds E from previous iteration)
        mm2z<TSTR>(T0, T1, W0, W1, tile);
#pragma unroll
        for (int j = 0; j < 16; j++) { W0[j] = T0[j]; W1[j] = T1[j]; }
        // kick2 of previous step, then kick1 of this step
        KICK();
        KICK();
        // E_step -> tile
        E_SECTION();
        // F <- F * E_step  (own rows; G reloaded, output into T)
        ld_row16(G0, Fs + q * 16);
        ld_row16(G1, Fs + r1 * 16);
        mm2z<TSTR>(T0, T1, G0, G1, tile);
        st_row16(Fs + q * 16, T0);
        st_row16(Fs + r1 * 16, T1);
    }

    // ===== final: S_out = sym(S0 * F) =====
    ld_row16(T0, Sigma + (size_t)p * 256 + q * 16);   // S0 rows (L2)
    ld_row16(T1, Sigma + (size_t)p * 256 + r1 * 16);
    __syncwarp();                                // all F rows written
    mm2z<16>(W0, W1, T0, T1, Fs);                // W = S0 * F
    put2(tile, q, W0, W1);                       // tile <- S_new (for transpose)
#pragma unroll
    for (int j = 0; j < 16; j++) {
        W0[j] = 0.5f * (W0[j] + tile[j * TSTR + q]);
        W1[j] = 0.5f * (W1[j] + tile[j * TSTR + r1]);
    }
    st_row16(Sig_o + (size_t)p * 256 + q * 16, W0);
    st_row16(Sig_o + (size_t)p * 256 + r1 * 16, W1);
}

extern "C" void kernel_launch(void* const* d_in, const int* in_sizes, int n_in,
                              void* d_out, int out_size) {
    const float* mu       = (const float*)d_in[0];
    const float* Sigma    = (const float*)d_in[1];
    const float* phi      = (const float*)d_in[2];
    const float* pi_mu    = (const float*)d_in[3];
    const float* pi_Sigma = (const float*)d_in[4];
    const float* pi_phi   = (const float*)d_in[5];
    const float* M_inv    = (const float*)d_in[6];

    const int npts = in_sizes[0] / 16;  // B*N = 32768
    float* out = (float*)d_out;
    float* mu_o  = out;
    float* Sig_o = out + (size_t)npts * 16;
    float* phi_o = out + (size_t)npts * 16 + (size_t)npts * 256;

    cudaFuncSetAttribute(ham_kernel, cudaFuncAttributeMaxDynamicSharedMemorySize,
                         SMEM_BYTES);

    dim3 grid(npts / PTS);
    dim3 block(NTHREADS);
    ham_kernel<<<grid, block, SMEM_BYTES>>>(mu, Sigma, phi, pi_mu, pi_Sigma,
                                            pi_phi, M_inv, mu_o, Sig_o, phi_o);
}